// round 16
// baseline (speedup 1.0000x reference)
#include <cuda_runtime.h>
#include <cuda_bf16.h>
#include <cstdint>

// LoKr via dense Kronecker factors + mma.sync (sm_100 baseline HMMA).
//   W1[l,m] = S*sum_j w1a[j,l] w1b[m,j];  W2[k,n] = sum_t w2a[t,k] w2b[n,t]
//   Per row: Y = W1 @ X @ W2^T.  Per PAIR of rows (Xp: 128 x 64, m' = ra*64+m):
//     GEMM1: T'[k, m'] = sum_n W2[k,n] Xp[m', n]      (64 x 128, K=n)
//     GEMM2: Y_ra[l, k] = sum_m W1[l,m] T'[k, ra*64+m] (2x 64x64, K=m)
//   fp32 accuracy via 3-term bf16 split (AhBh + AhBl + AlBh) per GEMM.
//   No transposes: both GEMMs' B operands are contiguous rows in smem.

static constexpr float SCALING = 1.0f / 16.0f;

// Pitches (bytes). 144 = 72 bf16 (64 data + 8 pad): ldmatrix rows walk banks
// 4r mod 32 -> conflict-free. 272 = 136 bf16 (128 data + 8 pad): same (68 = 4 mod 32).
static constexpr int PW = 144;
static constexpr int PD = 272;
static constexpr int OFF_W2H = 0,      OFF_W2L = 9216;    // 64 x 144
static constexpr int OFF_W1H = 18432,  OFF_W1L = 27648;   // 64 x 144
static constexpr int OFF_XH  = 36864,  OFF_XL  = 55296;   // 128 x 144
static constexpr int OFF_D1H = 73728,  OFF_D1L = 91136;   // 64 x 272
static constexpr int SMEM_BYTES = 108544;                 // -> 2 CTAs/SM

__device__ __forceinline__ uint32_t smem_u32(const void* p) {
    uint32_t a;
    asm("{ .reg .u64 t; cvta.to.shared.u64 t, %1; cvt.u32.u64 %0, t; }" : "=r"(a) : "l"(p));
    return a;
}
// pack {hi(high half), lo(low half)} -> bf16x2
__device__ __forceinline__ uint32_t pack_bf2(float lo, float hi) {
    uint32_t r; asm("cvt.rn.bf16x2.f32 %0, %1, %2;" : "=r"(r) : "f"(hi), "f"(lo)); return r;
}
// split (v0, v1) into hi-pair and residual lo-pair
__device__ __forceinline__ void split2(float v0, float v1, uint32_t& h, uint32_t& l) {
    h = pack_bf2(v0, v1);
    float r0 = v0 - __uint_as_float(h << 16);
    float r1 = v1 - __uint_as_float(h & 0xFFFF0000u);
    l = pack_bf2(r0, r1);
}
__device__ __forceinline__ void ldsm4(uint32_t* r, uint32_t addr) {
    asm volatile("ldmatrix.sync.aligned.m8n8.x4.shared.b16 {%0,%1,%2,%3}, [%4];"
                 : "=r"(r[0]), "=r"(r[1]), "=r"(r[2]), "=r"(r[3]) : "r"(addr));
}
__device__ __forceinline__ void mma_bf16(float* d, const uint32_t* a, uint32_t b0, uint32_t b1) {
    asm volatile("mma.sync.aligned.m16n8k16.row.col.f32.bf16.bf16.f32 "
                 "{%0,%1,%2,%3}, {%4,%5,%6,%7}, {%8,%9}, {%0,%1,%2,%3};"
                 : "+f"(d[0]), "+f"(d[1]), "+f"(d[2]), "+f"(d[3])
                 : "r"(a[0]), "r"(a[1]), "r"(a[2]), "r"(a[3]), "r"(b0), "r"(b1));
}
// A (row-major 16x16 tile at rowbase/colbase): groups 0..3 -> (m0-7,k0-7),(m8-15,k0-7),(m0-7,k8-15),(m8-15,k8-15)
__device__ __forceinline__ uint32_t addrA(uint32_t base, int rowbase, int colbase, int pitch, int lid) {
    int g = lid >> 3, ln = lid & 7;
    return base + (uint32_t)(rowbase + ((g & 1) << 3) + ln) * pitch + colbase * 2 + (g >> 1) * 16;
}
// B (col-major 16K x 16N; "columns" = contiguous K runs): groups -> (n0-7,k0-7),(n0-7,k8-15),(n8-15,k0-7),(n8-15,k8-15)
__device__ __forceinline__ uint32_t addrB(uint32_t base, int colbase, int kbase, int pitch, int lid) {
    int g = lid >> 3, ln = lid & 7;
    return base + (uint32_t)(colbase + ((g >> 1) << 3) + ln) * pitch + kbase * 2 + (g & 1) * 16;
}

__global__ void __launch_bounds__(256, 2) lokr_mma(
    const float* __restrict__ x,
    const float* __restrict__ w1a, const float* __restrict__ w1b,
    const float* __restrict__ w2a, const float* __restrict__ w2b,
    float* __restrict__ out, int rows)
{
    extern __shared__ __align__(16) char smem[];
    const uint32_t sb = smem_u32(smem);
    const int tid = threadIdx.x;
    const int wid = tid >> 5, lid = tid & 31;

    // ---- prologue: dense W1/W2, bf16 hi/lo, row-major pitch 144 ----
    {
        const int c = tid & 63, nb = tid >> 6;    // c = k (W2 row) / l (W1 row)
        float va[16], vb[16];
#pragma unroll
        for (int j = 0; j < 16; j++) {
            va[j] = __ldg(w2a + j * 64 + c);
            vb[j] = SCALING * __ldg(w1a + j * 64 + c);
        }
#pragma unroll
        for (int q = 0; q < 16; q++) {
            int nm = nb * 16 + q;                 // n (W2 col) / m (W1 col)
            float a2 = 0.f, a1 = 0.f;
#pragma unroll
            for (int j = 0; j < 16; j++) {
                a2 += va[j] * __ldg(w2b + nm * 16 + j);
                a1 += vb[j] * __ldg(w1b + nm * 16 + j);
            }
            __nv_bfloat16 h2 = __float2bfloat16_rn(a2);
            __nv_bfloat16 l2 = __float2bfloat16_rn(a2 - __bfloat162float(h2));
            __nv_bfloat16 h1 = __float2bfloat16_rn(a1);
            __nv_bfloat16 l1 = __float2bfloat16_rn(a1 - __bfloat162float(h1));
            uint32_t o = (uint32_t)c * PW + nm * 2;
            *reinterpret_cast<__nv_bfloat16*>(smem + OFF_W2H + o) = h2;
            *reinterpret_cast<__nv_bfloat16*>(smem + OFF_W2L + o) = l2;
            *reinterpret_cast<__nv_bfloat16*>(smem + OFF_W1H + o) = h1;
            *reinterpret_cast<__nv_bfloat16*>(smem + OFF_W1L + o) = l1;
        }
    }
    __syncthreads();

    const int nPairs = (rows + 1) >> 1;
    const int r4 = lid >> 2, c2 = (lid & 3) * 2;  // D-fragment row/col components

    for (int p = blockIdx.x; p < nPairs; p += gridDim.x) {
        // ---- stage X pair -> Xh/Xl (row m' x 64 n, pitch 144) ----
        {
            const float4* src = reinterpret_cast<const float4*>(x) + (size_t)p * 2048;
#pragma unroll
            for (int i = 0; i < 8; i++) {
                int g = tid + 256 * i;            // float4 idx 0..2047; row m' = g>>4
                float4 v = make_float4(0.f, 0.f, 0.f, 0.f);
                if (p * 2 + (g >> 10) < rows) v = __ldg(src + g);
                uint32_t h0, l0, h1, l1;
                split2(v.x, v.y, h0, l0);
                split2(v.z, v.w, h1, l1);
                uint32_t o = (uint32_t)(g >> 4) * PW + (g & 15) * 8;
                *reinterpret_cast<uint2*>(smem + OFF_XH + o) = make_uint2(h0, h1);
                *reinterpret_cast<uint2*>(smem + OFF_XL + o) = make_uint2(l0, l1);
            }
        }
        __syncthreads();   // sync1: X visible; prev GEMM2's D1 reads done

        // ---- GEMM1: T'[k, m'] = sum_n W2[k,n] Xp[m',n]  (M=64 k, N=128 m', K=64 n)
        // warp grid: wm = wid>>2 (k 32-slice), wn = wid&3 (m' 32-slice)
        {
            const int wm = wid >> 2, wn = wid & 3;
            float d1[2][4][4];
#pragma unroll
            for (int a = 0; a < 2; a++)
#pragma unroll
                for (int b = 0; b < 4; b++)
#pragma unroll
                    for (int c = 0; c < 4; c++) d1[a][b][c] = 0.f;

#pragma unroll
            for (int kt = 0; kt < 4; kt++) {      // K tiles (n)
                uint32_t ah[2][4], al[2][4];
#pragma unroll
                for (int mi = 0; mi < 2; mi++) {
                    ldsm4(ah[mi], addrA(sb + OFF_W2H, wm * 32 + mi * 16, kt * 16, PW, lid));
                    ldsm4(al[mi], addrA(sb + OFF_W2L, wm * 32 + mi * 16, kt * 16, PW, lid));
                }
#pragma unroll
                for (int bn = 0; bn < 2; bn++) {  // N16 groups
                    uint32_t bh[4], bl[4];
                    ldsm4(bh, addrB(sb + OFF_XH, wn * 32 + bn * 16, kt * 16, PW, lid));
                    ldsm4(bl, addrB(sb + OFF_XL, wn * 32 + bn * 16, kt * 16, PW, lid));
#pragma unroll
                    for (int mi = 0; mi < 2; mi++)
#pragma unroll
                        for (int sub = 0; sub < 2; sub++) {
                            float* dd = d1[mi][bn * 2 + sub];
                            mma_bf16(dd, ah[mi], bh[2 * sub], bh[2 * sub + 1]);
                            mma_bf16(dd, ah[mi], bl[2 * sub], bl[2 * sub + 1]);
                            mma_bf16(dd, al[mi], bh[2 * sub], bh[2 * sub + 1]);
                        }
                }
            }
            // store D1 (split): rows k, cols m' packed in pairs -> conflict-free u32 STS
#pragma unroll
            for (int mi = 0; mi < 2; mi++)
#pragma unroll
                for (int nj = 0; nj < 4; nj++) {
                    int k0 = wm * 32 + mi * 16 + r4;
                    int mp = wn * 32 + nj * 8 + c2;
                    uint32_t h, l;
                    split2(d1[mi][nj][0], d1[mi][nj][1], h, l);
                    *reinterpret_cast<uint32_t*>(smem + OFF_D1H + (uint32_t)k0 * PD + mp * 2) = h;
                    *reinterpret_cast<uint32_t*>(smem + OFF_D1L + (uint32_t)k0 * PD + mp * 2) = l;
                    split2(d1[mi][nj][2], d1[mi][nj][3], h, l);
                    *reinterpret_cast<uint32_t*>(smem + OFF_D1H + (uint32_t)(k0 + 8) * PD + mp * 2) = h;
                    *reinterpret_cast<uint32_t*>(smem + OFF_D1L + (uint32_t)(k0 + 8) * PD + mp * 2) = l;
                }
        }
        __syncthreads();   // sync2: D1 visible; X reads done

        // ---- GEMM2: Y_ra[l,k] = sum_m W1[l,m] D1[k, ra*64+m]  (2x 64x64, K=m)
        // warp: ra = wid>>2, l-slice = (wid&3)*16
        {
            const int ra = wid >> 2, lbase = (wid & 3) * 16;
            float d2[8][4];
#pragma unroll
            for (int a = 0; a < 8; a++)
#pragma unroll
                for (int c = 0; c < 4; c++) d2[a][c] = 0.f;

#pragma unroll
            for (int kt = 0; kt < 4; kt++) {      // K tiles (m)
                uint32_t ah[4], al[4];
                ldsm4(ah, addrA(sb + OFF_W1H, lbase, kt * 16, PW, lid));
                ldsm4(al, addrA(sb + OFF_W1L, lbase, kt * 16, PW, lid));
#pragma unroll
                for (int bg = 0; bg < 4; bg++) {  // N16 groups (k_out)
                    uint32_t bh[4], bl[4];
                    ldsm4(bh, addrB(sb + OFF_D1H, bg * 16, ra * 64 + kt * 16, PD, lid));
                    ldsm4(bl, addrB(sb + OFF_D1L, bg * 16, ra * 64 + kt * 16, PD, lid));
#pragma unroll
                    for (int sub = 0; sub < 2; sub++) {
                        float* dd = d2[bg * 2 + sub];
                        mma_bf16(dd, ah, bh[2 * sub], bh[2 * sub + 1]);
                        mma_bf16(dd, ah, bl[2 * sub], bl[2 * sub + 1]);
                        mma_bf16(dd, al, bh[2 * sub], bh[2 * sub + 1]);
                    }
                }
            }
            // writeback: out[p*2+ra][l*64 + k], float2 per fragment row
            int row = p * 2 + ra;
            if (row < rows) {
                float* orow = out + (size_t)row * 4096;
#pragma unroll
                for (int j = 0; j < 8; j++) {
                    int l0 = lbase + r4, k = j * 8 + c2;
                    *reinterpret_cast<float2*>(orow + l0 * 64 + k) =
                        make_float2(d2[j][0], d2[j][1]);
                    *reinterpret_cast<float2*>(orow + (l0 + 8) * 64 + k) =
                        make_float2(d2[j][2], d2[j][3]);
                }
            }
        }
        // no third sync: next stage writes X (last read before sync2);
        // next GEMM1 writes D1 only after next sync1 (all GEMM2 reads done).
    }
}

extern "C" void kernel_launch(void* const* d_in, const int* in_sizes, int n_in,
                              void* d_out, int out_size) {
    const float* x   = (const float*)d_in[0];
    const float* w1a = (const float*)d_in[1];
    const float* w1b = (const float*)d_in[2];
    const float* w2a = (const float*)d_in[3];
    const float* w2b = (const float*)d_in[4];
    float* out = (float*)d_out;

    int rows = in_sizes[0] / 4096;
    int nPairs = (rows + 1) >> 1;

    cudaFuncSetAttribute(lokr_mma, cudaFuncAttributeMaxDynamicSharedMemorySize, SMEM_BYTES);
    int grid = nPairs < 296 ? nPairs : 296;   // 148 SMs x 2 CTAs
    lokr_mma<<<grid, 256, SMEM_BYTES>>>(x, w1a, w1b, w2a, w2b, out, rows);
}

// round 17
// speedup vs baseline: 1.1258x; 1.1258x over previous
#include <cuda_runtime.h>
#include <cuda_bf16.h>
#include <cstdint>

// LoKr, rank-structured tensor-core version (sm_100 baseline mma.sync).
//   Y_row = W1 @ X_row @ W2^T  with  W2^T = w2b @ w2a, W1 = S*w1a^T w1b^T (dense fp32)
//   Per PAIR of rows (Xp: 128 x 64, m' = ra*64 + m):
//     G1 (tensor): U[m',t]  = sum_n Xp[m',n] w2b[n,t]      M=128 N=16 K=64
//     MID (SIMT):  V[l',t]  = sum_m W1[l,m] U[ra*64+m, t]  fp32 exact
//     G2 (tensor): Y_ra[l,k]= sum_t V[l',t] w2a[t,k]       M=128 N=64 K=16
//   3-term bf16 split (AhBh + AhBl + AlBh) on G1 and G2; middle is fp32.

static constexpr float SCALING = 1.0f / 16.0f;

// pitches (bytes)
static constexpr int PW  = 144;  // X h/l, w2bT h/l rows (64 bf16 + pad; 16B-mult)
static constexpr int PUB = 80;   // U fp32 rows (16 f32 + pad)
static constexpr int PV  = 48;   // V h/l, w2aT h/l rows (16 bf16 + pad; 16B-mult)
static constexpr int PW1 = 260;  // W1 fp32 rows (65 words: conflict-free column walks)

static constexpr int OFF_XH    = 0;       // 128 x 144
static constexpr int OFF_XL    = 18432;
static constexpr int OFF_U     = 36864;   // 128 x 80 (fp32)
static constexpr int OFF_VH    = 47104;   // 128 x 48
static constexpr int OFF_VL    = 53248;
static constexpr int OFF_W1    = 59392;   // 64 x 260 (fp32)
static constexpr int OFF_W2BTH = 76032;   // 16 x 144
static constexpr int OFF_W2BTL = 78336;
static constexpr int OFF_W2ATH = 80640;   // 64 x 48
static constexpr int OFF_W2ATL = 83712;
static constexpr int SMEM_BYTES = 86784;  // -> 2 CTAs/SM

__device__ __forceinline__ uint32_t smem_u32(const void* p) {
    uint32_t a;
    asm("{ .reg .u64 t; cvta.to.shared.u64 t, %1; cvt.u32.u64 %0, t; }" : "=r"(a) : "l"(p));
    return a;
}
__device__ __forceinline__ uint32_t pack_bf2(float lo, float hi) {
    uint32_t r; asm("cvt.rn.bf16x2.f32 %0, %1, %2;" : "=r"(r) : "f"(hi), "f"(lo)); return r;
}
__device__ __forceinline__ void split2(float v0, float v1, uint32_t& h, uint32_t& l) {
    h = pack_bf2(v0, v1);
    float r0 = v0 - __uint_as_float(h << 16);
    float r1 = v1 - __uint_as_float(h & 0xFFFF0000u);
    l = pack_bf2(r0, r1);
}
__device__ __forceinline__ void split1(float v, __nv_bfloat16& h, __nv_bfloat16& l) {
    h = __float2bfloat16_rn(v);
    l = __float2bfloat16_rn(v - __bfloat162float(h));
}
__device__ __forceinline__ void ldsm4(uint32_t* r, uint32_t addr) {
    asm volatile("ldmatrix.sync.aligned.m8n8.x4.shared.b16 {%0,%1,%2,%3}, [%4];"
                 : "=r"(r[0]), "=r"(r[1]), "=r"(r[2]), "=r"(r[3]) : "r"(addr));
}
__device__ __forceinline__ void mma_bf16(float* d, const uint32_t* a, uint32_t b0, uint32_t b1) {
    asm volatile("mma.sync.aligned.m16n8k16.row.col.f32.bf16.bf16.f32 "
                 "{%0,%1,%2,%3}, {%4,%5,%6,%7}, {%8,%9}, {%0,%1,%2,%3};"
                 : "+f"(d[0]), "+f"(d[1]), "+f"(d[2]), "+f"(d[3])
                 : "r"(a[0]), "r"(a[1]), "r"(a[2]), "r"(a[3]), "r"(b0), "r"(b1));
}
__device__ __forceinline__ float2 ffma2(float2 a, float2 b, float2 c) {
    float2 d;
    asm("{\n\t.reg .b64 ra, rb, rc, rd;\n\t"
        "mov.b64 ra, {%2,%3};\n\tmov.b64 rb, {%4,%5};\n\tmov.b64 rc, {%6,%7};\n\t"
        "fma.rn.f32x2 rd, ra, rb, rc;\n\tmov.b64 {%0,%1}, rd;\n\t}"
        : "=f"(d.x), "=f"(d.y)
        : "f"(a.x), "f"(a.y), "f"(b.x), "f"(b.y), "f"(c.x), "f"(c.y));
    return d;
}
// A tile (row-major M x K): verified mapping from R16
__device__ __forceinline__ uint32_t addrA(uint32_t base, int rowbase, int colbase, int pitch, int lid) {
    int g = lid >> 3, ln = lid & 7;
    return base + (uint32_t)(rowbase + ((g & 1) << 3) + ln) * pitch + colbase * 2 + (g >> 1) * 16;
}
// B tile (rows = N index, K contiguous within row): verified mapping from R16
__device__ __forceinline__ uint32_t addrB(uint32_t base, int colbase, int kbase, int pitch, int lid) {
    int g = lid >> 3, ln = lid & 7;
    return base + (uint32_t)(colbase + ((g >> 1) << 3) + ln) * pitch + kbase * 2 + (g & 1) * 16;
}

__global__ void __launch_bounds__(256, 2) lokr_rk(
    const float* __restrict__ x,
    const float* __restrict__ w1a, const float* __restrict__ w1b,
    const float* __restrict__ w2a, const float* __restrict__ w2b,
    float* __restrict__ out, int rows)
{
    extern __shared__ __align__(16) char smem[];
    const uint32_t sb = smem_u32(smem);
    const int tid = threadIdx.x;
    const int wid = tid >> 5, lid = tid & 31;
    const int r4 = lid >> 2, c2 = (lid & 3) * 2;

    // ---- prologue ----
    {   // W1 dense fp32: W1[l][m] = S * sum_j w1a[j,l] w1b[m,j]; pitch 65 words
        const int l = tid & 63, nb = tid >> 6;
        float va[16];
#pragma unroll
        for (int j = 0; j < 16; j++) va[j] = SCALING * __ldg(w1a + j * 64 + l);
#pragma unroll
        for (int q = 0; q < 16; q++) {
            int m = nb * 16 + q;
            float a1 = 0.f;
#pragma unroll
            for (int j = 0; j < 16; j++) a1 += va[j] * __ldg(w1b + m * 16 + j);
            *reinterpret_cast<float*>(smem + OFF_W1 + ((uint32_t)l * 65 + m) * 4) = a1;
        }
        // w2bT[t][n] split, pitch 144
        const int t16 = tid & 15, n4 = tid >> 4;
#pragma unroll
        for (int i = 0; i < 4; i++) {
            int n = n4 * 4 + i;
            float v = __ldg(w2b + n * 16 + t16);
            __nv_bfloat16 h, lo; split1(v, h, lo);
            *reinterpret_cast<__nv_bfloat16*>(smem + OFF_W2BTH + t16 * PW + n * 2) = h;
            *reinterpret_cast<__nv_bfloat16*>(smem + OFF_W2BTL + t16 * PW + n * 2) = lo;
        }
        // w2aT[k][t] split, pitch 48
        const int k64 = tid & 63, tq = tid >> 6;
#pragma unroll
        for (int i = 0; i < 4; i++) {
            int t = tq * 4 + i;
            float v = __ldg(w2a + t * 64 + k64);
            __nv_bfloat16 h, lo; split1(v, h, lo);
            *reinterpret_cast<__nv_bfloat16*>(smem + OFF_W2ATH + k64 * PV + t * 2) = h;
            *reinterpret_cast<__nv_bfloat16*>(smem + OFF_W2ATL + k64 * PV + t * 2) = lo;
        }
    }
    __syncthreads();

    // G2's B operand is loop-invariant: hoist into registers (4 bg x 4 regs x h/l)
    uint32_t g2bh[4][4], g2bl[4][4];
#pragma unroll
    for (int bg = 0; bg < 4; bg++) {
        ldsm4(g2bh[bg], addrB(sb + OFF_W2ATH, bg * 16, 0, PV, lid));
        ldsm4(g2bl[bg], addrB(sb + OFF_W2ATL, bg * 16, 0, PV, lid));
    }

    const int nPairs = (rows + 1) >> 1;

    for (int p = blockIdx.x; p < nPairs; p += gridDim.x) {
        // ---- stage X pair -> Xh/Xl [m'][n], pitch 144 (R16-verified) ----
        {
            const float4* src = reinterpret_cast<const float4*>(x) + (size_t)p * 2048;
#pragma unroll
            for (int i = 0; i < 8; i++) {
                int g = tid + 256 * i;
                float4 v = make_float4(0.f, 0.f, 0.f, 0.f);
                if (p * 2 + (g >> 10) < rows) v = __ldg(src + g);
                uint32_t h0, l0, h1, l1;
                split2(v.x, v.y, h0, l0);
                split2(v.z, v.w, h1, l1);
                uint32_t o = (uint32_t)(g >> 4) * PW + (g & 15) * 8;
                *reinterpret_cast<uint2*>(smem + OFF_XH + o) = make_uint2(h0, h1);
                *reinterpret_cast<uint2*>(smem + OFF_XL + o) = make_uint2(l0, l1);
            }
        }
        __syncthreads();   // sync1: X visible; prev G1's U writes race-free (see tail note)

        // ---- G1: U[m',t] = sum_n Xp[m',n] w2b[n,t]  (M=128 N=16 K=64) ----
        {
            float du0[4] = {0.f, 0.f, 0.f, 0.f};   // t 0-7
            float du1[4] = {0.f, 0.f, 0.f, 0.f};   // t 8-15
#pragma unroll
            for (int kt = 0; kt < 4; kt++) {
                uint32_t ah[4], al[4], bh[4], bl[4];
                ldsm4(ah, addrA(sb + OFF_XH, wid * 16, kt * 16, PW, lid));
                ldsm4(al, addrA(sb + OFF_XL, wid * 16, kt * 16, PW, lid));
                ldsm4(bh, addrB(sb + OFF_W2BTH, 0, kt * 16, PW, lid));
                ldsm4(bl, addrB(sb + OFF_W2BTL, 0, kt * 16, PW, lid));
                mma_bf16(du0, ah, bh[0], bh[1]);
                mma_bf16(du0, ah, bl[0], bl[1]);
                mma_bf16(du0, al, bh[0], bh[1]);
                mma_bf16(du1, ah, bh[2], bh[3]);
                mma_bf16(du1, ah, bl[2], bl[3]);
                mma_bf16(du1, al, bh[2], bh[3]);
            }
            // store U fp32 [m'][t], pitch 20 words
            int row = wid * 16 + r4;
            *reinterpret_cast<float2*>(smem + OFF_U + (uint32_t)row * PUB + c2 * 4) =
                make_float2(du0[0], du0[1]);
            *reinterpret_cast<float2*>(smem + OFF_U + (uint32_t)(row + 8) * PUB + c2 * 4) =
                make_float2(du0[2], du0[3]);
            *reinterpret_cast<float2*>(smem + OFF_U + (uint32_t)row * PUB + (8 + c2) * 4) =
                make_float2(du1[0], du1[1]);
            *reinterpret_cast<float2*>(smem + OFF_U + (uint32_t)(row + 8) * PUB + (8 + c2) * 4) =
                make_float2(du1[2], du1[3]);
        }
        __syncthreads();   // sync2: U visible; X reads done

        // ---- MID (SIMT fp32): V[l',t] = sum_m W1[l,m] U[ra*64+m, t]; split to bf16 ----
        {
            const int lp = tid >> 1, tp = tid & 1;     // l' 0..127, t-half
            const int ra = lp >> 6, l = lp & 63;
            const float* W1row = reinterpret_cast<const float*>(smem + OFF_W1) + l * 65;
            const float* Ub = reinterpret_cast<const float*>(smem + OFF_U) + ra * 64 * 20 + tp * 8;
            float2 acc0 = {0.f, 0.f}, acc1 = {0.f, 0.f}, acc2 = {0.f, 0.f}, acc3 = {0.f, 0.f};
#pragma unroll 8
            for (int m = 0; m < 64; m++) {
                float w = W1row[m];
                float2 wd = make_float2(w, w);
                const float2* Um = reinterpret_cast<const float2*>(Ub + m * 20);
                acc0 = ffma2(wd, Um[0], acc0);
                acc1 = ffma2(wd, Um[1], acc1);
                acc2 = ffma2(wd, Um[2], acc2);
                acc3 = ffma2(wd, Um[3], acc3);
            }
            uint32_t h, lo;
            uint32_t vbase = (uint32_t)lp * PV + tp * 16;
            split2(acc0.x, acc0.y, h, lo);
            *reinterpret_cast<uint32_t*>(smem + OFF_VH + vbase + 0) = h;
            *reinterpret_cast<uint32_t*>(smem + OFF_VL + vbase + 0) = lo;
            split2(acc1.x, acc1.y, h, lo);
            *reinterpret_cast<uint32_t*>(smem + OFF_VH + vbase + 4) = h;
            *reinterpret_cast<uint32_t*>(smem + OFF_VL + vbase + 4) = lo;
            split2(acc2.x, acc2.y, h, lo);
            *reinterpret_cast<uint32_t*>(smem + OFF_VH + vbase + 8) = h;
            *reinterpret_cast<uint32_t*>(smem + OFF_VL + vbase + 8) = lo;
            split2(acc3.x, acc3.y, h, lo);
            *reinterpret_cast<uint32_t*>(smem + OFF_VH + vbase + 12) = h;
            *reinterpret_cast<uint32_t*>(smem + OFF_VL + vbase + 12) = lo;
        }
        __syncthreads();   // sync3: V visible; U reads done

        // ---- G2: Y_ra[l,k] = sum_t V[l',t] w2a[t,k]  (M=128 N=64 K=16) ----
        {
            uint32_t ah[4], al[4];
            ldsm4(ah, addrA(sb + OFF_VH, wid * 16, 0, PV, lid));
            ldsm4(al, addrA(sb + OFF_VL, wid * 16, 0, PV, lid));
            const int ra = wid >> 2, lb = (wid & 3) * 16;
            const int row = p * 2 + ra;
            float* orow = out + (size_t)row * 4096;
            const bool ok = (row < rows);
#pragma unroll
            for (int bg = 0; bg < 4; bg++) {
#pragma unroll
                for (int sub = 0; sub < 2; sub++) {
                    float d2[4] = {0.f, 0.f, 0.f, 0.f};
                    mma_bf16(d2, ah, g2bh[bg][2 * sub], g2bh[bg][2 * sub + 1]);
                    mma_bf16(d2, ah, g2bl[bg][2 * sub], g2bl[bg][2 * sub + 1]);
                    mma_bf16(d2, al, g2bh[bg][2 * sub], g2bh[bg][2 * sub + 1]);
                    if (ok) {
                        int k = bg * 16 + sub * 8 + c2, l0 = lb + r4;
                        *reinterpret_cast<float2*>(orow + l0 * 64 + k) = make_float2(d2[0], d2[1]);
                        *reinterpret_cast<float2*>(orow + (l0 + 8) * 64 + k) = make_float2(d2[2], d2[3]);
                    }
                }
            }
        }
        // Tail note: next staging writes X (last read before sync2); next G1 writes U
        // only after next sync1, and V reads of U ended before sync3; V rewritten only
        // after next sync2 while G2 reads end before any warp passes next sync2. Safe.
    }
}

extern "C" void kernel_launch(void* const* d_in, const int* in_sizes, int n_in,
                              void* d_out, int out_size) {
    const float* x   = (const float*)d_in[0];
    const float* w1a = (const float*)d_in[1];
    const float* w1b = (const float*)d_in[2];
    const float* w2a = (const float*)d_in[3];
    const float* w2b = (const float*)d_in[4];
    float* out = (float*)d_out;

    int rows = in_sizes[0] / 4096;
    int nPairs = (rows + 1) >> 1;

    cudaFuncSetAttribute(lokr_rk, cudaFuncAttributeMaxDynamicSharedMemorySize, SMEM_BYTES);
    int grid = nPairs < 296 ? nPairs : 296;   // 148 SMs x 2 CTAs
    lokr_rk<<<grid, 256, SMEM_BYTES>>>(x, w1a, w1b, w2a, w2b, out, rows);
}